// round 12
// baseline (speedup 1.0000x reference)
#include <cuda_runtime.h>
#include <cuda_bf16.h>
#include <cstdint>

// Problem constants
#define N        8192
#define IN_DIM   512
#define NCLASS   16
#define PC       512      // per class
#define KK       256      // kept per class
#define NSEL     4096     // NCLASS * KK

// Output layout (single f32 buffer): M_out | X_out | mask_out
#define M_OUT_OFF    0
#define X_OUT_OFF    (NSEL * (size_t)NSEL)               // 16777216
#define MASK_OUT_OFF (X_OUT_OFF + NSEL * (size_t)IN_DIM) // 18874368

// Persistent moutx grid: 3 blocks/SM * 148 SMs
#define PGRID 444

// Scratch (device globals — no allocation allowed)
__device__ int   g_idx[NSEL];
__device__ float g_vals[NSEL];

// ---------------------------------------------------------------------------
// Bit-replica of XLA:CPU / Eigen Cephes expf (confirmed bit-exact: R5 w=0).
// ---------------------------------------------------------------------------
__device__ __forceinline__ float cephes_expf(float r) {
    float in = fminf(fmaxf(r, -88.3762626647949f), 88.3762626647950f);
    float fx = floorf(__fmaf_rn(in, 1.44269504088896341f, 0.5f));
    float tmp = __fmul_rn(0.693359375f, fx);
    float zz  = __fmul_rn(-2.12194440e-4f, fx);
    float x   = __fsub_rn(__fsub_rn(in, tmp), zz);
    float z2  = __fmul_rn(x, x);
    float y   = __fmaf_rn(x, 1.9875691500E-4f, 1.3981999507E-3f);
    y = __fmaf_rn(y, x, 8.3334519073E-3f);
    y = __fmaf_rn(y, x, 4.1665795894E-2f);
    y = __fmaf_rn(y, x, 1.6666665459E-1f);
    y = __fmaf_rn(y, x, 5.0000001201E-1f);
    y = __fmaf_rn(y, z2, x);
    y = __fadd_rn(1.0f, y);
    int n = (int)fx;
    float pow2n = __int_as_float((unsigned)(n + 127) << 23);
    return __fmul_rn(y, pow2n);
}

__device__ __forceinline__ float warp_dot_reduce(float s) {
#pragma unroll
    for (int o = 16; o > 0; o >>= 1)
        s += __shfl_xor_sync(0xffffffffu, s, o);
    return s;
}

__device__ __forceinline__ unsigned long long cex_shfl(unsigned long long v,
                                                       int s, bool asc, int e) {
    unsigned long long o = __shfl_xor_sync(0xffffffffu, v, s);
    bool lower   = (e & s) == 0;
    bool keepMin = (lower == asc);
    return keepMin ? (o < v ? o : v) : (o > v ? o : v);
}

// ---------------------------------------------------------------------------
// Fused class kernel: one block per class (16 blocks x 512 threads).
//  1) per-warp is64 ballot (warp-uniform, barrier-free)
//  2) scan mask, collect this class's 512 member rows (SMEM atomics;
//     collection order irrelevant: sort key (score_bits<<32)|idx is total,
//     so the final order is deterministic = jax top_k tie-break)
//  3) 512 member dots: W in registers, 2 rows in flight per warp
//  4) Cephes sigmoid (bit-exact) -> packed keys
//  5) hybrid shfl/SMEM bitonic sort, keep 256 smallest
// ---------------------------------------------------------------------------
__global__ __launch_bounds__(PC) void class_kernel(const float* __restrict__ X,
                                                   const float* __restrict__ W,
                                                   const float* __restrict__ b,
                                                   const int* __restrict__ mask_i32,
                                                   float* __restrict__ out) {
    __shared__ int s_list[PC];
    __shared__ int s_cnt;
    __shared__ unsigned long long keys[PC];

    const int j    = blockIdx.x;
    const int tid  = threadIdx.x;
    const int wrp  = tid >> 5;
    const int lane = tid & 31;

    // (1) is64: odd int32 words of the first 32 entries all zero <=> int64.
    int nz = (mask_i32[2 * lane + 1] != 0);
    const int is64 = (__ballot_sync(0xffffffffu, nz) == 0u) ? 1 : 0;

    if (tid == 0) s_cnt = 0;
    __syncthreads();

    // (2) member collection
#pragma unroll
    for (int it = 0; it < N / PC; ++it) {
        int i = it * PC + tid;
        int cls = is64 ? mask_i32[2 * i] : mask_i32[i];
        if (cls == j) {
            int p = atomicAdd(&s_cnt, 1);
            s_list[p] = i;
        }
    }
    __syncthreads();

    // (3+4) dots: warp w handles slots [w*32, w*32+32), 2 rows in flight
    const float4* w4 = (const float4*)W;
    float4 q0 = __ldg(&w4[lane +  0]), q1 = __ldg(&w4[lane + 32]),
           q2 = __ldg(&w4[lane + 64]), q3 = __ldg(&w4[lane + 96]);
    const float bb = b[0];

    for (int k = 0; k < 32; k += 2) {
        int slotA = wrp * 32 + k;
        int slotB = slotA + 1;
        int rowA = s_list[slotA];
        int rowB = s_list[slotB];
        const float4* xa = (const float4*)(X + (size_t)rowA * IN_DIM);
        const float4* xb = (const float4*)(X + (size_t)rowB * IN_DIM);
        float4 a0 = xa[lane], a1 = xa[lane + 32], a2 = xa[lane + 64], a3 = xa[lane + 96];
        float4 c0 = xb[lane], c1 = xb[lane + 32], c2 = xb[lane + 64], c3 = xb[lane + 96];

        float sa0 = __fmul_rn(a0.x, q0.x), sa1 = __fmul_rn(a0.y, q0.y);
        float sa2 = __fmul_rn(a0.z, q0.z), sa3 = __fmul_rn(a0.w, q0.w);
        sa0 = __fmaf_rn(a1.x, q1.x, sa0); sa1 = __fmaf_rn(a1.y, q1.y, sa1);
        sa2 = __fmaf_rn(a1.z, q1.z, sa2); sa3 = __fmaf_rn(a1.w, q1.w, sa3);
        sa0 = __fmaf_rn(a2.x, q2.x, sa0); sa1 = __fmaf_rn(a2.y, q2.y, sa1);
        sa2 = __fmaf_rn(a2.z, q2.z, sa2); sa3 = __fmaf_rn(a2.w, q2.w, sa3);
        sa0 = __fmaf_rn(a3.x, q3.x, sa0); sa1 = __fmaf_rn(a3.y, q3.y, sa1);
        sa2 = __fmaf_rn(a3.z, q3.z, sa2); sa3 = __fmaf_rn(a3.w, q3.w, sa3);
        float sa = __fadd_rn(__fadd_rn(sa0, sa1), __fadd_rn(sa2, sa3));

        float sb0 = __fmul_rn(c0.x, q0.x), sb1 = __fmul_rn(c0.y, q0.y);
        float sb2 = __fmul_rn(c0.z, q0.z), sb3 = __fmul_rn(c0.w, q0.w);
        sb0 = __fmaf_rn(c1.x, q1.x, sb0); sb1 = __fmaf_rn(c1.y, q1.y, sb1);
        sb2 = __fmaf_rn(c1.z, q1.z, sb2); sb3 = __fmaf_rn(c1.w, q1.w, sb3);
        sb0 = __fmaf_rn(c2.x, q2.x, sb0); sb1 = __fmaf_rn(c2.y, q2.y, sb1);
        sb2 = __fmaf_rn(c2.z, q2.z, sb2); sb3 = __fmaf_rn(c2.w, q2.w, sb3);
        sb0 = __fmaf_rn(c3.x, q3.x, sb0); sb1 = __fmaf_rn(c3.y, q3.y, sb1);
        sb2 = __fmaf_rn(c3.z, q3.z, sb2); sb3 = __fmaf_rn(c3.w, q3.w, sb3);
        float sb = __fadd_rn(__fadd_rn(sb0, sb1), __fadd_rn(sb2, sb3));

        sa = warp_dot_reduce(sa);
        sb = warp_dot_reduce(sb);

        if (lane == 0) {
            float xA = __fdiv_rn(__fadd_rn(sa, bb), 100.0f);
            float xB = __fdiv_rn(__fadd_rn(sb, bb), 100.0f);
            float scA = __fdiv_rn(1.0f, __fadd_rn(1.0f, cephes_expf(-xA)));
            float scB = __fdiv_rn(1.0f, __fadd_rn(1.0f, cephes_expf(-xB)));
            keys[slotA] = ((unsigned long long)__float_as_uint(scA) << 32) | (unsigned)rowA;
            keys[slotB] = ((unsigned long long)__float_as_uint(scB) << 32) | (unsigned)rowB;
        }
    }
    __syncthreads();

    // (5) hybrid bitonic sort (intra-warp via shfl; 10 cross-warp SMEM stages)
    unsigned long long v = keys[tid];
#pragma unroll
    for (unsigned k = 2; k <= 32; k <<= 1) {
        bool asc = ((tid & k) == 0);
        for (int s = k >> 1; s >= 1; s >>= 1)
            v = cex_shfl(v, s, asc, tid);
    }
    keys[tid] = v;

#pragma unroll
    for (unsigned k = 64; k <= PC; k <<= 1) {
        for (unsigned s = k >> 1; s >= 32; s >>= 1) {
            __syncthreads();
            unsigned partner = tid ^ s;
            if (partner > (unsigned)tid) {
                unsigned long long a  = keys[tid];
                unsigned long long bo = keys[partner];
                bool ascending = ((tid & k) == 0);
                if ((a > bo) == ascending) {
                    keys[tid]     = bo;
                    keys[partner] = a;
                }
            }
        }
        __syncthreads();
        v = keys[tid];
        bool asc = ((tid & k) == 0);
#pragma unroll
        for (int s = 16; s >= 1; s >>= 1)
            v = cex_shfl(v, s, asc, tid);
        keys[tid] = v;
    }

    if (tid < KK) {
        int o = j * KK + tid;
        g_idx[o]  = (int)(unsigned)(v & 0xffffffffu);
        g_vals[o] = __uint_as_float((unsigned)(v >> 32));
        out[MASK_OUT_OFF + o] = (float)j;   // mask[idx] == class id by construction
    }
}

// ---------------------------------------------------------------------------
// cp.async helpers
// ---------------------------------------------------------------------------
__device__ __forceinline__ void cp_async16(uint32_t saddr, const void* gptr) {
    asm volatile("cp.async.cg.shared.global [%0], [%1], 16;\n"
                 :: "r"(saddr), "l"(gptr));
}
__device__ __forceinline__ void cp_commit() {
    asm volatile("cp.async.commit_group;\n");
}
template <int NN>
__device__ __forceinline__ void cp_wait() {
    asm volatile("cp.async.wait_group %0;\n" :: "n"(NN));
}
__device__ __forceinline__ void stcs4(float* p, float4 v) {
    asm volatile("st.global.cs.v4.f32 [%0], {%1,%2,%3,%4};\n"
                 :: "l"(p), "f"(v.x), "f"(v.y), "f"(v.z), "f"(v.w));
}

// ---------------------------------------------------------------------------
// Kernel 2 (persistent, pipelined): grid = 444 blocks (3/SM, single wave).
// Block i processes rows i, i+444, ... with a double-buffered cp.async
// pipeline; streaming stores for never-re-read output.
//   X_out[r,:] = X[idx[r],:] * vals[r]
//   M_out[r,c] = M[idx[r], idx[c]]
// ---------------------------------------------------------------------------
extern __shared__ float s_buf[];   // [2][N]

__device__ __forceinline__ void issue_row(const float* __restrict__ M,
                                          int ri, int bufsel) {
    uint32_t sbase = (uint32_t)__cvta_generic_to_shared(&s_buf[bufsel * N]);
    const char* g = (const char*)(M + (size_t)ri * N);
    int t = threadIdx.x;
#pragma unroll
    for (int i = 0; i < 4; ++i) {
        int off16 = (t + i * 512) * 16;
        cp_async16(sbase + off16, g + off16);
    }
    cp_commit();
}

__global__ __launch_bounds__(512) void moutx_kernel(const float* __restrict__ M,
                                                    const float* __restrict__ X,
                                                    float* __restrict__ out) {
    const int t = threadIdx.x;
    const int r0 = blockIdx.x;

    if (r0 < NSEL)          issue_row(M, g_idx[r0], 0);
    if (r0 + PGRID < NSEL)  issue_row(M, g_idx[r0 + PGRID], 1);

    int buf = 0;
    for (int r = r0; r < NSEL; r += PGRID, buf ^= 1) {
        int nn = r + 2 * PGRID;
        if (nn < NSEL) { cp_wait<1>(); } else { cp_wait<0>(); }
        __syncthreads();

        if (t < 128) {
            float v = g_vals[r];
            float4 x = ((const float4*)(X + (size_t)g_idx[r] * IN_DIM))[t];
            stcs4((float*)(((float4*)(out + X_OUT_OFF + (size_t)r * IN_DIM)) + t),
                  make_float4(x.x * v, x.y * v, x.z * v, x.w * v));
        }

        const float* row = &s_buf[buf * N];
        float4* dst4 = (float4*)(out + M_OUT_OFF + (size_t)r * NSEL);
        const int4* gi4 = (const int4*)g_idx;
#pragma unroll
        for (int i = 0; i < 2; ++i) {
            int c = t + i * 512;
            int4 ii = gi4[c];
            float4 o;
            o.x = row[ii.x];
            o.y = row[ii.y];
            o.z = row[ii.z];
            o.w = row[ii.w];
            stcs4((float*)(dst4 + c), o);
        }
        __syncthreads();              // buffer fully consumed before refill

        if (nn < NSEL) issue_row(M, g_idx[nn], buf);
    }
}

// ---------------------------------------------------------------------------
extern "C" void kernel_launch(void* const* d_in, const int* in_sizes, int n_in,
                              void* d_out, int out_size) {
    const float* M    = (const float*)d_in[0];
    const float* X    = (const float*)d_in[1];
    const int*   mask = (const int*)  d_in[2];
    const float* W    = (const float*)d_in[3];
    const float* b    = (const float*)d_in[4];
    float* out = (float*)d_out;

    static const size_t MOUT_SMEM = 2 * N * sizeof(float);   // 64 KB
    cudaFuncSetAttribute(moutx_kernel,
                         cudaFuncAttributeMaxDynamicSharedMemorySize,
                         (int)MOUT_SMEM);

    class_kernel<<<NCLASS, PC>>>(X, W, b, mask, out);
    moutx_kernel<<<PGRID, 512, MOUT_SMEM>>>(M, X, out);
}

// round 13
// speedup vs baseline: 1.6957x; 1.6957x over previous
#include <cuda_runtime.h>
#include <cuda_bf16.h>
#include <cstdint>

// Problem constants
#define N        8192
#define IN_DIM   512
#define NCLASS   16
#define PC       512      // per class
#define KK       256      // kept per class
#define NSEL     4096     // NCLASS * KK

// Output layout (single f32 buffer): M_out | X_out | mask_out
#define M_OUT_OFF    0
#define X_OUT_OFF    (NSEL * (size_t)NSEL)               // 16777216
#define MASK_OUT_OFF (X_OUT_OFF + NSEL * (size_t)IN_DIM) // 18874368

// Persistent moutx grid: 3 blocks/SM * 148 SMs
#define PGRID 444

// Scratch (device globals — no allocation allowed)
// Counters padded to 256B stride: each class in its own L2 slice (R10 win).
#define CNT_STRIDE 64
__device__ int                g_idx[NSEL];
__device__ float              g_vals[NSEL];
__device__ unsigned           g_cnt[NCLASS * CNT_STRIDE];   // monotone; pos = old & 511
__device__ unsigned long long g_keys[N];

// ---------------------------------------------------------------------------
// Bit-replica of XLA:CPU / Eigen Cephes expf (confirmed bit-exact: R5 w=0).
// ---------------------------------------------------------------------------
__device__ __forceinline__ float cephes_expf(float r) {
    float in = fminf(fmaxf(r, -88.3762626647949f), 88.3762626647950f);
    float fx = floorf(__fmaf_rn(in, 1.44269504088896341f, 0.5f));
    float tmp = __fmul_rn(0.693359375f, fx);
    float zz  = __fmul_rn(-2.12194440e-4f, fx);
    float x   = __fsub_rn(__fsub_rn(in, tmp), zz);
    float z2  = __fmul_rn(x, x);
    float y   = __fmaf_rn(x, 1.9875691500E-4f, 1.3981999507E-3f);
    y = __fmaf_rn(y, x, 8.3334519073E-3f);
    y = __fmaf_rn(y, x, 4.1665795894E-2f);
    y = __fmaf_rn(y, x, 1.6666665459E-1f);
    y = __fmaf_rn(y, x, 5.0000001201E-1f);
    y = __fmaf_rn(y, z2, x);
    y = __fadd_rn(1.0f, y);
    int n = (int)fx;
    float pow2n = __int_as_float((unsigned)(n + 127) << 23);
    return __fmul_rn(y, pow2n);
}

// ---------------------------------------------------------------------------
// Kernel 1 (fused detect + score + scatter): TWO rows per warp (grid 512).
// 12 independent 16B loads in flight per warp; shfl tree + Cephes sigmoid
// (bit-exact) amortized over 2 rows. Scatter hits 256B-strided counters.
// ---------------------------------------------------------------------------
__global__ void score_kernel(const float* __restrict__ X,
                             const float* __restrict__ W,
                             const float* __restrict__ b,
                             const int* __restrict__ mask_i32) {
    __shared__ unsigned warp_any[8];
    __shared__ int s_is64;

    const int t    = threadIdx.x;          // 0..255
    const int wid  = t >> 5;
    const int lane = t & 31;

    const int rowA = blockIdx.x * 16 + wid * 2;
    const int rowB = rowA + 1;
    const float4* xa = (const float4*)(X + (size_t)rowA * IN_DIM);
    const float4* xb = (const float4*)(X + (size_t)rowB * IN_DIM);
    const float4* w4 = (const float4*)W;

    float4 a0 = xa[lane], a1 = xa[lane + 32], a2 = xa[lane + 64], a3 = xa[lane + 96];
    float4 c0 = xb[lane], c1 = xb[lane + 32], c2 = xb[lane + 64], c3 = xb[lane + 96];
    float4 q0 = __ldg(&w4[lane +  0]), q1 = __ldg(&w4[lane + 32]),
           q2 = __ldg(&w4[lane + 64]), q3 = __ldg(&w4[lane + 96]);

    // embedded is64 detection (first 128 odd int32 words all zero?)
    int nz = (mask_i32[2 * (t & 127) + 1] != 0);
    unsigned any = __ballot_sync(0xffffffffu, nz);
    if (lane == 0) warp_any[wid] = any;

    float sa0 = __fmul_rn(a0.x, q0.x), sa1 = __fmul_rn(a0.y, q0.y);
    float sa2 = __fmul_rn(a0.z, q0.z), sa3 = __fmul_rn(a0.w, q0.w);
    sa0 = __fmaf_rn(a1.x, q1.x, sa0); sa1 = __fmaf_rn(a1.y, q1.y, sa1);
    sa2 = __fmaf_rn(a1.z, q1.z, sa2); sa3 = __fmaf_rn(a1.w, q1.w, sa3);
    sa0 = __fmaf_rn(a2.x, q2.x, sa0); sa1 = __fmaf_rn(a2.y, q2.y, sa1);
    sa2 = __fmaf_rn(a2.z, q2.z, sa2); sa3 = __fmaf_rn(a2.w, q2.w, sa3);
    sa0 = __fmaf_rn(a3.x, q3.x, sa0); sa1 = __fmaf_rn(a3.y, q3.y, sa1);
    sa2 = __fmaf_rn(a3.z, q3.z, sa2); sa3 = __fmaf_rn(a3.w, q3.w, sa3);
    float sa = __fadd_rn(__fadd_rn(sa0, sa1), __fadd_rn(sa2, sa3));

    float sb0 = __fmul_rn(c0.x, q0.x), sb1 = __fmul_rn(c0.y, q0.y);
    float sb2 = __fmul_rn(c0.z, q0.z), sb3 = __fmul_rn(c0.w, q0.w);
    sb0 = __fmaf_rn(c1.x, q1.x, sb0); sb1 = __fmaf_rn(c1.y, q1.y, sb1);
    sb2 = __fmaf_rn(c1.z, q1.z, sb2); sb3 = __fmaf_rn(c1.w, q1.w, sb3);
    sb0 = __fmaf_rn(c2.x, q2.x, sb0); sb1 = __fmaf_rn(c2.y, q2.y, sb1);
    sb2 = __fmaf_rn(c2.z, q2.z, sb2); sb3 = __fmaf_rn(c2.w, q2.w, sb3);
    sb0 = __fmaf_rn(c3.x, q3.x, sb0); sb1 = __fmaf_rn(c3.y, q3.y, sb1);
    sb2 = __fmaf_rn(c3.z, q3.z, sb2); sb3 = __fmaf_rn(c3.w, q3.w, sb3);
    float sb = __fadd_rn(__fadd_rn(sb0, sb1), __fadd_rn(sb2, sb3));

#pragma unroll
    for (int o = 16; o > 0; o >>= 1) {
        sa += __shfl_xor_sync(0xffffffffu, sa, o);
        sb += __shfl_xor_sync(0xffffffffu, sb, o);
    }

    __syncthreads();
    if (t == 0) {
        unsigned a = 0;
#pragma unroll
        for (int w = 0; w < 8; ++w) a |= warp_any[w];
        s_is64 = (a == 0u) ? 1 : 0;
    }
    __syncthreads();
    const int is64 = s_is64;

    if (lane == 0) {
        const float bb = b[0];
        float xA = __fdiv_rn(__fadd_rn(sa, bb), 100.0f);
        float xB = __fdiv_rn(__fadd_rn(sb, bb), 100.0f);
        float scA = __fdiv_rn(1.0f, __fadd_rn(1.0f, cephes_expf(-xA)));
        float scB = __fdiv_rn(1.0f, __fadd_rn(1.0f, cephes_expf(-xB)));
        int clsA = is64 ? mask_i32[2 * rowA] : mask_i32[rowA];
        int clsB = is64 ? mask_i32[2 * rowB] : mask_i32[rowB];
        unsigned pA = atomicAdd(&g_cnt[clsA * CNT_STRIDE], 1u) & (PC - 1);
        g_keys[clsA * PC + pA] =
            ((unsigned long long)__float_as_uint(scA) << 32) | (unsigned)rowA;
        unsigned pB = atomicAdd(&g_cnt[clsB * CNT_STRIDE], 1u) & (PC - 1);
        g_keys[clsB * PC + pB] =
            ((unsigned long long)__float_as_uint(scB) << 32) | (unsigned)rowB;
    }
}

// ---------------------------------------------------------------------------
// Hybrid bitonic sort, 512 keys/class, one block (512 thr) per class.
// ---------------------------------------------------------------------------
__device__ __forceinline__ unsigned long long cex_shfl(unsigned long long v,
                                                       int s, bool asc, int e) {
    unsigned long long o = __shfl_xor_sync(0xffffffffu, v, s);
    bool lower   = (e & s) == 0;
    bool keepMin = (lower == asc);
    return keepMin ? (o < v ? o : v) : (o > v ? o : v);
}

__global__ __launch_bounds__(PC) void sort_kernel(float* __restrict__ out) {
    __shared__ unsigned long long keys[PC];
    const int j   = blockIdx.x;
    const int tid = threadIdx.x;

    unsigned long long v = g_keys[j * PC + tid];

#pragma unroll
    for (unsigned k = 2; k <= 32; k <<= 1) {
        bool asc = ((tid & k) == 0);
        for (int s = k >> 1; s >= 1; s >>= 1)
            v = cex_shfl(v, s, asc, tid);
    }
    keys[tid] = v;

#pragma unroll
    for (unsigned k = 64; k <= PC; k <<= 1) {
        for (unsigned s = k >> 1; s >= 32; s >>= 1) {
            __syncthreads();
            unsigned partner = tid ^ s;
            if (partner > (unsigned)tid) {
                unsigned long long a  = keys[tid];
                unsigned long long bb = keys[partner];
                bool ascending = ((tid & k) == 0);
                if ((a > bb) == ascending) {
                    keys[tid]     = bb;
                    keys[partner] = a;
                }
            }
        }
        __syncthreads();
        v = keys[tid];
        bool asc = ((tid & k) == 0);
#pragma unroll
        for (int s = 16; s >= 1; s >>= 1)
            v = cex_shfl(v, s, asc, tid);
        keys[tid] = v;
    }

    if (tid < KK) {
        int o = j * KK + tid;
        g_idx[o]  = (int)(unsigned)(v & 0xffffffffu);
        g_vals[o] = __uint_as_float((unsigned)(v >> 32));
        out[MASK_OUT_OFF + o] = (float)j;   // mask[idx] == class id by construction
    }
}

// ---------------------------------------------------------------------------
// cp.async helpers
// ---------------------------------------------------------------------------
__device__ __forceinline__ void cp_async16(uint32_t saddr, const void* gptr) {
    asm volatile("cp.async.cg.shared.global [%0], [%1], 16;\n"
                 :: "r"(saddr), "l"(gptr));
}
__device__ __forceinline__ void cp_commit() {
    asm volatile("cp.async.commit_group;\n");
}
template <int NN>
__device__ __forceinline__ void cp_wait() {
    asm volatile("cp.async.wait_group %0;\n" :: "n"(NN));
}
__device__ __forceinline__ void stcs4(float* p, float4 v) {
    asm volatile("st.global.cs.v4.f32 [%0], {%1,%2,%3,%4};\n"
                 :: "l"(p), "f"(v.x), "f"(v.y), "f"(v.z), "f"(v.w));
}

// ---------------------------------------------------------------------------
// Kernel 3 (persistent, pipelined; confirmed at the LTS/DRAM floor):
// grid = 444 blocks (3/SM, single wave); block i handles rows i, i+444, ...
// with a double-buffered cp.async pipeline; streaming stores.
//   X_out[r,:] = X[idx[r],:] * vals[r]
//   M_out[r,c] = M[idx[r], idx[c]]
// ---------------------------------------------------------------------------
extern __shared__ float s_buf[];   // [2][N]

__device__ __forceinline__ void issue_row(const float* __restrict__ M,
                                          int ri, int bufsel) {
    uint32_t sbase = (uint32_t)__cvta_generic_to_shared(&s_buf[bufsel * N]);
    const char* g = (const char*)(M + (size_t)ri * N);
    int t = threadIdx.x;
#pragma unroll
    for (int i = 0; i < 4; ++i) {
        int off16 = (t + i * 512) * 16;
        cp_async16(sbase + off16, g + off16);
    }
    cp_commit();
}

__global__ __launch_bounds__(512) void moutx_kernel(const float* __restrict__ M,
                                                    const float* __restrict__ X,
                                                    float* __restrict__ out) {
    const int t = threadIdx.x;
    const int r0 = blockIdx.x;

    if (r0 < NSEL)          issue_row(M, g_idx[r0], 0);
    if (r0 + PGRID < NSEL)  issue_row(M, g_idx[r0 + PGRID], 1);

    int buf = 0;
    for (int r = r0; r < NSEL; r += PGRID, buf ^= 1) {
        int nn = r + 2 * PGRID;
        if (nn < NSEL) { cp_wait<1>(); } else { cp_wait<0>(); }
        __syncthreads();

        if (t < 128) {
            float v = g_vals[r];
            float4 x = ((const float4*)(X + (size_t)g_idx[r] * IN_DIM))[t];
            stcs4((float*)(((float4*)(out + X_OUT_OFF + (size_t)r * IN_DIM)) + t),
                  make_float4(x.x * v, x.y * v, x.z * v, x.w * v));
        }

        const float* row = &s_buf[buf * N];
        float4* dst4 = (float4*)(out + M_OUT_OFF + (size_t)r * NSEL);
        const int4* gi4 = (const int4*)g_idx;
#pragma unroll
        for (int i = 0; i < 2; ++i) {
            int c = t + i * 512;
            int4 ii = gi4[c];
            float4 o;
            o.x = row[ii.x];
            o.y = row[ii.y];
            o.z = row[ii.z];
            o.w = row[ii.w];
            stcs4((float*)(dst4 + c), o);
        }
        __syncthreads();              // buffer fully consumed before refill

        if (nn < NSEL) issue_row(M, g_idx[nn], buf);
    }
}

// ---------------------------------------------------------------------------
extern "C" void kernel_launch(void* const* d_in, const int* in_sizes, int n_in,
                              void* d_out, int out_size) {
    const float* M    = (const float*)d_in[0];
    const float* X    = (const float*)d_in[1];
    const int*   mask = (const int*)  d_in[2];
    const float* W    = (const float*)d_in[3];
    const float* b    = (const float*)d_in[4];
    float* out = (float*)d_out;

    static const size_t MOUT_SMEM = 2 * N * sizeof(float);   // 64 KB
    cudaFuncSetAttribute(moutx_kernel,
                         cudaFuncAttributeMaxDynamicSharedMemorySize,
                         (int)MOUT_SMEM);

    score_kernel<<<N / 16, 256>>>(X, W, b, mask);   // 2 rows per warp
    sort_kernel<<<NCLASS, PC>>>(out);
    moutx_kernel<<<PGRID, 512, MOUT_SMEM>>>(M, X, out);
}

// round 14
// speedup vs baseline: 1.7100x; 1.0085x over previous
#include <cuda_runtime.h>
#include <cuda_bf16.h>
#include <cstdint>

// Problem constants
#define N        8192
#define IN_DIM   512
#define NCLASS   16
#define PC       512      // per class
#define KK       256      // kept per class
#define NSEL     4096     // NCLASS * KK

// Output layout (single f32 buffer): M_out | X_out | mask_out
#define M_OUT_OFF    0
#define X_OUT_OFF    (NSEL * (size_t)NSEL)               // 16777216
#define MASK_OUT_OFF (X_OUT_OFF + NSEL * (size_t)IN_DIM) // 18874368

// Persistent moutx grid: 3 blocks/SM * 148 SMs
#define PGRID 444
// Fused score+sort grid
#define SGRID 256

// Scratch (device globals — no allocation allowed)
#define CNT_STRIDE 64
__device__ int                g_idx[NSEL];
__device__ float              g_vals[NSEL];
__device__ unsigned           g_cnt[NCLASS * CNT_STRIDE];  // monotone; pos = old & 511
__device__ unsigned           g_done;                      // monotone; mult of SGRID between runs
__device__ unsigned long long g_keys[N];

// ---------------------------------------------------------------------------
// Bit-replica of XLA:CPU / Eigen Cephes expf (confirmed bit-exact: R5 w=0).
// ---------------------------------------------------------------------------
__device__ __forceinline__ float cephes_expf(float r) {
    float in = fminf(fmaxf(r, -88.3762626647949f), 88.3762626647950f);
    float fx = floorf(__fmaf_rn(in, 1.44269504088896341f, 0.5f));
    float tmp = __fmul_rn(0.693359375f, fx);
    float zz  = __fmul_rn(-2.12194440e-4f, fx);
    float x   = __fsub_rn(__fsub_rn(in, tmp), zz);
    float z2  = __fmul_rn(x, x);
    float y   = __fmaf_rn(x, 1.9875691500E-4f, 1.3981999507E-3f);
    y = __fmaf_rn(y, x, 8.3334519073E-3f);
    y = __fmaf_rn(y, x, 4.1665795894E-2f);
    y = __fmaf_rn(y, x, 1.6666665459E-1f);
    y = __fmaf_rn(y, x, 5.0000001201E-1f);
    y = __fmaf_rn(y, z2, x);
    y = __fadd_rn(1.0f, y);
    int n = (int)fx;
    float pow2n = __int_as_float((unsigned)(n + 127) << 23);
    return __fmul_rn(y, pow2n);
}

__device__ __forceinline__ unsigned long long cex_shfl(unsigned long long v,
                                                       int s, bool asc, int e) {
    unsigned long long o = __shfl_xor_sync(0xffffffffu, v, s);
    bool lower   = (e & s) == 0;
    bool keepMin = (lower == asc);
    return keepMin ? (o < v ? o : v) : (o > v ? o : v);
}

// ---------------------------------------------------------------------------
// Kernel 1 (fused score + scatter + global barrier + per-class sort).
// Grid 256 x 512 threads. Each block: 16 warps x 2 rows = 32 rows.
//  - warp-local is64 ballot (warp-uniform, barrier-free)
//  - vectorized dot (12 independent 16B loads/warp), Cephes sigmoid
//  - scatter keys via 256B-strided counters (R10 win)
//  - __threadfence + atomicAdd(g_done); blocks 0..15 spin for all 256
//    arrivals of THIS run (base = old - old%SGRID; counter stays
//    == 0 mod SGRID between graph replays), then sort class blockIdx.
// Deadlock-free: non-sorters exit unconditionally; 444 resident slots.
// ---------------------------------------------------------------------------
__global__ __launch_bounds__(512) void score_sort_kernel(
        const float* __restrict__ X,
        const float* __restrict__ W,
        const float* __restrict__ b,
        const int* __restrict__ mask_i32,
        float* __restrict__ out) {
    __shared__ unsigned long long keys[PC];
    __shared__ unsigned s_target;

    const int tid  = threadIdx.x;          // 0..511
    const int wid  = tid >> 5;
    const int lane = tid & 31;

    // warp-local is64 detection: odd int32 words of first 32 entries all 0?
    int nz = (mask_i32[2 * lane + 1] != 0);
    const int is64 = (__ballot_sync(0xffffffffu, nz) == 0u) ? 1 : 0;

    // --- score 2 rows per warp ---
    const int rowA = blockIdx.x * 32 + wid * 2;
    const int rowB = rowA + 1;
    const float4* xa = (const float4*)(X + (size_t)rowA * IN_DIM);
    const float4* xb = (const float4*)(X + (size_t)rowB * IN_DIM);
    const float4* w4 = (const float4*)W;

    float4 a0 = xa[lane], a1 = xa[lane + 32], a2 = xa[lane + 64], a3 = xa[lane + 96];
    float4 c0 = xb[lane], c1 = xb[lane + 32], c2 = xb[lane + 64], c3 = xb[lane + 96];
    float4 q0 = __ldg(&w4[lane +  0]), q1 = __ldg(&w4[lane + 32]),
           q2 = __ldg(&w4[lane + 64]), q3 = __ldg(&w4[lane + 96]);

    float sa0 = __fmul_rn(a0.x, q0.x), sa1 = __fmul_rn(a0.y, q0.y);
    float sa2 = __fmul_rn(a0.z, q0.z), sa3 = __fmul_rn(a0.w, q0.w);
    sa0 = __fmaf_rn(a1.x, q1.x, sa0); sa1 = __fmaf_rn(a1.y, q1.y, sa1);
    sa2 = __fmaf_rn(a1.z, q1.z, sa2); sa3 = __fmaf_rn(a1.w, q1.w, sa3);
    sa0 = __fmaf_rn(a2.x, q2.x, sa0); sa1 = __fmaf_rn(a2.y, q2.y, sa1);
    sa2 = __fmaf_rn(a2.z, q2.z, sa2); sa3 = __fmaf_rn(a2.w, q2.w, sa3);
    sa0 = __fmaf_rn(a3.x, q3.x, sa0); sa1 = __fmaf_rn(a3.y, q3.y, sa1);
    sa2 = __fmaf_rn(a3.z, q3.z, sa2); sa3 = __fmaf_rn(a3.w, q3.w, sa3);
    float sa = __fadd_rn(__fadd_rn(sa0, sa1), __fadd_rn(sa2, sa3));

    float sb0 = __fmul_rn(c0.x, q0.x), sb1 = __fmul_rn(c0.y, q0.y);
    float sb2 = __fmul_rn(c0.z, q0.z), sb3 = __fmul_rn(c0.w, q0.w);
    sb0 = __fmaf_rn(c1.x, q1.x, sb0); sb1 = __fmaf_rn(c1.y, q1.y, sb1);
    sb2 = __fmaf_rn(c1.z, q1.z, sb2); sb3 = __fmaf_rn(c1.w, q1.w, sb3);
    sb0 = __fmaf_rn(c2.x, q2.x, sb0); sb1 = __fmaf_rn(c2.y, q2.y, sb1);
    sb2 = __fmaf_rn(c2.z, q2.z, sb2); sb3 = __fmaf_rn(c2.w, q2.w, sb3);
    sb0 = __fmaf_rn(c3.x, q3.x, sb0); sb1 = __fmaf_rn(c3.y, q3.y, sb1);
    sb2 = __fmaf_rn(c3.z, q3.z, sb2); sb3 = __fmaf_rn(c3.w, q3.w, sb3);
    float sb = __fadd_rn(__fadd_rn(sb0, sb1), __fadd_rn(sb2, sb3));

#pragma unroll
    for (int o = 16; o > 0; o >>= 1) {
        sa += __shfl_xor_sync(0xffffffffu, sa, o);
        sb += __shfl_xor_sync(0xffffffffu, sb, o);
    }

    if (lane == 0) {
        const float bbv = b[0];
        float xA = __fdiv_rn(__fadd_rn(sa, bbv), 100.0f);
        float xB = __fdiv_rn(__fadd_rn(sb, bbv), 100.0f);
        float scA = __fdiv_rn(1.0f, __fadd_rn(1.0f, cephes_expf(-xA)));
        float scB = __fdiv_rn(1.0f, __fadd_rn(1.0f, cephes_expf(-xB)));
        int clsA = is64 ? mask_i32[2 * rowA] : mask_i32[rowA];
        int clsB = is64 ? mask_i32[2 * rowB] : mask_i32[rowB];
        unsigned pA = atomicAdd(&g_cnt[clsA * CNT_STRIDE], 1u) & (PC - 1);
        g_keys[clsA * PC + pA] =
            ((unsigned long long)__float_as_uint(scA) << 32) | (unsigned)rowA;
        unsigned pB = atomicAdd(&g_cnt[clsB * CNT_STRIDE], 1u) & (PC - 1);
        g_keys[clsB * PC + pB] =
            ((unsigned long long)__float_as_uint(scB) << 32) | (unsigned)rowB;
    }
    __syncthreads();

    // --- global barrier arrival ---
    if (tid == 0) {
        __threadfence();
        unsigned old = atomicAdd(&g_done, 1u);
        s_target = old - (old % SGRID) + SGRID;
    }

    if (blockIdx.x >= NCLASS) return;      // non-sorters exit

    __syncthreads();
    if (tid == 0) {
        unsigned tgt = s_target;
        volatile unsigned* dp = &g_done;
        while (*dp < tgt) { }
        __threadfence();
    }
    __syncthreads();

    // --- per-class hybrid bitonic sort (class j = blockIdx.x) ---
    const int j = blockIdx.x;
    unsigned long long v = g_keys[j * PC + tid];

#pragma unroll
    for (unsigned k = 2; k <= 32; k <<= 1) {
        bool asc = ((tid & k) == 0);
        for (int s = k >> 1; s >= 1; s >>= 1)
            v = cex_shfl(v, s, asc, tid);
    }
    keys[tid] = v;

#pragma unroll
    for (unsigned k = 64; k <= PC; k <<= 1) {
        for (unsigned s = k >> 1; s >= 32; s >>= 1) {
            __syncthreads();
            unsigned partner = tid ^ s;
            if (partner > (unsigned)tid) {
                unsigned long long a  = keys[tid];
                unsigned long long bo = keys[partner];
                bool ascending = ((tid & k) == 0);
                if ((a > bo) == ascending) {
                    keys[tid]     = bo;
                    keys[partner] = a;
                }
            }
        }
        __syncthreads();
        v = keys[tid];
        bool asc = ((tid & k) == 0);
#pragma unroll
        for (int s = 16; s >= 1; s >>= 1)
            v = cex_shfl(v, s, asc, tid);
        keys[tid] = v;
    }

    if (tid < KK) {
        int o = j * KK + tid;
        g_idx[o]  = (int)(unsigned)(v & 0xffffffffu);
        g_vals[o] = __uint_as_float((unsigned)(v >> 32));
        out[MASK_OUT_OFF + o] = (float)j;   // mask[idx] == class id by construction
    }
}

// ---------------------------------------------------------------------------
// cp.async helpers
// ---------------------------------------------------------------------------
__device__ __forceinline__ void cp_async16(uint32_t saddr, const void* gptr) {
    asm volatile("cp.async.cg.shared.global [%0], [%1], 16;\n"
                 :: "r"(saddr), "l"(gptr));
}
__device__ __forceinline__ void cp_commit() {
    asm volatile("cp.async.commit_group;\n");
}
template <int NN>
__device__ __forceinline__ void cp_wait() {
    asm volatile("cp.async.wait_group %0;\n" :: "n"(NN));
}
__device__ __forceinline__ void stcs4(float* p, float4 v) {
    asm volatile("st.global.cs.v4.f32 [%0], {%1,%2,%3,%4};\n"
                 :: "l"(p), "f"(v.x), "f"(v.y), "f"(v.z), "f"(v.w));
}

// ---------------------------------------------------------------------------
// Kernel 2 (persistent, pipelined; confirmed at the mixed R/W HBM floor):
// grid = 444 blocks (3/SM, single wave); block i handles rows i, i+444, ...
// with a double-buffered cp.async pipeline; streaming stores.
//   X_out[r,:] = X[idx[r],:] * vals[r]
//   M_out[r,c] = M[idx[r], idx[c]]
// ---------------------------------------------------------------------------
extern __shared__ float s_buf[];   // [2][N]

__device__ __forceinline__ void issue_row(const float* __restrict__ M,
                                          int ri, int bufsel) {
    uint32_t sbase = (uint32_t)__cvta_generic_to_shared(&s_buf[bufsel * N]);
    const char* g = (const char*)(M + (size_t)ri * N);
    int t = threadIdx.x;
#pragma unroll
    for (int i = 0; i < 4; ++i) {
        int off16 = (t + i * 512) * 16;
        cp_async16(sbase + off16, g + off16);
    }
    cp_commit();
}

__global__ __launch_bounds__(512) void moutx_kernel(const float* __restrict__ M,
                                                    const float* __restrict__ X,
                                                    float* __restrict__ out) {
    const int t = threadIdx.x;
    const int r0 = blockIdx.x;

    if (r0 < NSEL)          issue_row(M, g_idx[r0], 0);
    if (r0 + PGRID < NSEL)  issue_row(M, g_idx[r0 + PGRID], 1);

    int buf = 0;
    for (int r = r0; r < NSEL; r += PGRID, buf ^= 1) {
        int nn = r + 2 * PGRID;
        if (nn < NSEL) { cp_wait<1>(); } else { cp_wait<0>(); }
        __syncthreads();

        if (t < 128) {
            float v = g_vals[r];
            float4 x = ((const float4*)(X + (size_t)g_idx[r] * IN_DIM))[t];
            stcs4((float*)(((float4*)(out + X_OUT_OFF + (size_t)r * IN_DIM)) + t),
                  make_float4(x.x * v, x.y * v, x.z * v, x.w * v));
        }

        const float* row = &s_buf[buf * N];
        float4* dst4 = (float4*)(out + M_OUT_OFF + (size_t)r * NSEL);
        const int4* gi4 = (const int4*)g_idx;
#pragma unroll
        for (int i = 0; i < 2; ++i) {
            int c = t + i * 512;
            int4 ii = gi4[c];
            float4 o;
            o.x = row[ii.x];
            o.y = row[ii.y];
            o.z = row[ii.z];
            o.w = row[ii.w];
            stcs4((float*)(dst4 + c), o);
        }
        __syncthreads();              // buffer fully consumed before refill

        if (nn < NSEL) issue_row(M, g_idx[nn], buf);
    }
}

// ---------------------------------------------------------------------------
extern "C" void kernel_launch(void* const* d_in, const int* in_sizes, int n_in,
                              void* d_out, int out_size) {
    const float* M    = (const float*)d_in[0];
    const float* X    = (const float*)d_in[1];
    const int*   mask = (const int*)  d_in[2];
    const float* W    = (const float*)d_in[3];
    const float* b    = (const float*)d_in[4];
    float* out = (float*)d_out;

    static const size_t MOUT_SMEM = 2 * N * sizeof(float);   // 64 KB
    cudaFuncSetAttribute(moutx_kernel,
                         cudaFuncAttributeMaxDynamicSharedMemorySize,
                         (int)MOUT_SMEM);

    score_sort_kernel<<<SGRID, 512>>>(X, W, b, mask, out);
    moutx_kernel<<<PGRID, 512, MOUT_SMEM>>>(M, X, out);
}